// round 2
// baseline (speedup 1.0000x reference)
#include <cuda_runtime.h>
#include <cstdint>

// Problem constants (from reference setup_inputs)
#define B_DIM 2
#define T_DIM 1024
#define H_DIM 32
#define P_DIM 64
#define N_DIM 128
#define L_CH 64
#define K_CH 16          // T / L_CH
#define BH (B_DIM * H_DIM)
#define Y_SIZE (B_DIM * T_DIM * H_DIM * P_DIM)
#define FS_SIZE (BH * P_DIM * N_DIM)
#define NSPLIT 8

// Scratch (no cudaMalloc allowed)
__device__ float g_Acs[BH * T_DIM];                       // global inclusive cumsum of A per (b,h)
__device__ float g_part[NSPLIT * BH * P_DIM * N_DIM];     // split partials for final_state

// ---------------------------------------------------------------------------
// Kernel 1: per-(b,h) inclusive cumsum of A over T (Hillis-Steele in smem)
// ---------------------------------------------------------------------------
__global__ void __launch_bounds__(1024) acs_kernel(const float* __restrict__ A) {
    int bh = blockIdx.x;
    int b = bh >> 5, h = bh & 31;
    __shared__ float buf[2][T_DIM];
    int t = threadIdx.x;
    buf[0][t] = A[(size_t)(b * T_DIM + t) * H_DIM + h];
    __syncthreads();
    int src = 0;
    for (int off = 1; off < T_DIM; off <<= 1) {
        float v = buf[src][t];
        if (t >= off) v += buf[src][t - off];
        buf[src ^ 1][t] = v;
        src ^= 1;
        __syncthreads();
    }
    g_Acs[bh * T_DIM + t] = buf[src][t];
}

// ---------------------------------------------------------------------------
// Kernel 2: main fused masked-attention over lower-triangle 64x64 tiles.
// Block = one (b,h, row-tile r). Loops col tiles c = 0..r:
//   S = C_r @ B_c^T  (n=128 inner)
//   M = exp(Acs_i - Acs_j) + msf*Lmask   (j<=i; 0 above diag in diag tile)
//   Y_r += (S .* M) @ x_c
// ---------------------------------------------------------------------------
#define PC 132   // padded pitch for 128-wide tiles (floats)
#define PX 68    // padded pitch for 64-wide tiles

__global__ void __launch_bounds__(256, 2) ssd_main_kernel(
    const float* __restrict__ xg, const float* __restrict__ Bg,
    const float* __restrict__ Cg, const float* __restrict__ Lm,
    const float* __restrict__ msfp, float* __restrict__ Yg)
{
    const int r  = (K_CH - 1) - blockIdx.x;   // longest blocks first
    const int bh = blockIdx.y;
    const int b  = bh >> 5, h = bh & 31;
    const float msf = *msfp;

    extern __shared__ float sm[];
    float* sC = sm;                 // 64 * PC
    float* sB = sC + 64 * PC;       // 64 * PC
    float* sX = sB + 64 * PC;       // 64 * PX
    float* sS = sX + 64 * PX;       // 64 * PX
    float* aR = sS + 64 * PX;       // 64
    float* aC = aR + 64;            // 64

    const int tid = threadIdx.x;
    const int i2  = tid >> 4;       // 0..15 (row group)
    const int j2  = tid & 15;       // 0..15 (col group)

    const float* acs = g_Acs + (size_t)bh * T_DIM;

    // Load C row-tile (64 x 128) once
    for (int idx = tid; idx < 64 * 32; idx += 256) {
        int row = idx >> 5, q = idx & 31;
        *(float4*)(sC + row * PC + q * 4) =
            *(const float4*)(Cg + ((size_t)((b * T_DIM + r * L_CH + row) * H_DIM) + h) * N_DIM + q * 4);
    }
    if (tid < 64) aR[tid] = acs[r * L_CH + tid];

    float y[4][4];
#pragma unroll
    for (int a = 0; a < 4; a++)
#pragma unroll
        for (int c2 = 0; c2 < 4; c2++) y[a][c2] = 0.f;

    for (int cc = 0; cc <= r; ++cc) {
        __syncthreads();   // protect sB/sX/sS reuse
        // Load B col-tile (64 x 128) and x col-tile (64 x 64)
        for (int idx = tid; idx < 64 * 32; idx += 256) {
            int row = idx >> 5, q = idx & 31;
            *(float4*)(sB + row * PC + q * 4) =
                *(const float4*)(Bg + ((size_t)((b * T_DIM + cc * L_CH + row) * H_DIM) + h) * N_DIM + q * 4);
        }
        for (int idx = tid; idx < 64 * 16; idx += 256) {
            int row = idx >> 4, q = idx & 15;
            *(float4*)(sX + row * PX + q * 4) =
                *(const float4*)(xg + ((size_t)((b * T_DIM + cc * L_CH + row) * H_DIM) + h) * P_DIM + q * 4);
        }
        if (tid < 64) aC[tid] = acs[cc * L_CH + tid];
        __syncthreads();

        // Stage 1: S[li][lj] = C_r[li,:] . B_c[lj,:]
        float s[4][4];
#pragma unroll
        for (int a = 0; a < 4; a++)
#pragma unroll
            for (int c2 = 0; c2 < 4; c2++) s[a][c2] = 0.f;

#pragma unroll 2
        for (int n = 0; n < N_DIM; n += 4) {
            float4 av[4], bv[4];
#pragma unroll
            for (int di = 0; di < 4; di++)
                av[di] = *(const float4*)(sC + (i2 + 16 * di) * PC + n);
#pragma unroll
            for (int dj = 0; dj < 4; dj++)
                bv[dj] = *(const float4*)(sB + (j2 + 16 * dj) * PC + n);
#pragma unroll
            for (int di = 0; di < 4; di++)
#pragma unroll
                for (int dj = 0; dj < 4; dj++) {
                    s[di][dj] += av[di].x * bv[dj].x + av[di].y * bv[dj].y
                               + av[di].z * bv[dj].z + av[di].w * bv[dj].w;
                }
        }

        // Mask: M = exp(Acs_i - Acs_j) + msf*Lmask ; diag tile zeroes j>i
        const bool diag = (cc == r);
        const float* Lrow = Lm + ((size_t)bh * T_DIM + (size_t)r * L_CH) * T_DIM + (size_t)cc * L_CH;
#pragma unroll
        for (int di = 0; di < 4; di++) {
            int li = i2 + 16 * di;
            float ar = aR[li];
#pragma unroll
            for (int dj = 0; dj < 4; dj++) {
                int lj = j2 + 16 * dj;
                float f = 0.f;
                if (!diag || lj <= li)
                    f = __expf(ar - aC[lj]) + msf * Lrow[(size_t)li * T_DIM + lj];
                sS[li * PX + lj] = s[di][dj] * f;
            }
        }
        __syncthreads();

        // Stage 2: Y += Ms @ X  (inner over 64 cols of the tile)
#pragma unroll 2
        for (int j = 0; j < L_CH; ++j) {
            float a0[4], b0[4];
#pragma unroll
            for (int di = 0; di < 4; di++) a0[di] = sS[(i2 + 16 * di) * PX + j];
#pragma unroll
            for (int dj = 0; dj < 4; dj++) b0[dj] = sX[j * PX + j2 + 16 * dj];
#pragma unroll
            for (int di = 0; di < 4; di++)
#pragma unroll
                for (int dj = 0; dj < 4; dj++)
                    y[di][dj] += a0[di] * b0[dj];
        }
    }

    // Write Y tile: Y[b, r*64+li, h, p]
#pragma unroll
    for (int di = 0; di < 4; di++) {
        int li = i2 + 16 * di;
#pragma unroll
        for (int dj = 0; dj < 4; dj++) {
            int p = j2 + 16 * dj;
            Yg[((size_t)((b * T_DIM + r * L_CH + li) * H_DIM) + h) * P_DIM + p] = y[di][dj];
        }
    }
}

// ---------------------------------------------------------------------------
// Kernel 3: final_state partials. split over T, 128 t's per block.
// fs[p,n] = sum_t exp(Acs_T - Acs_t) * x[t,p] * B[t,n]
// ---------------------------------------------------------------------------
__global__ void __launch_bounds__(256) state_kernel(
    const float* __restrict__ xg, const float* __restrict__ Bg)
{
    int split = blockIdx.x;
    int bh    = blockIdx.y;
    int b = bh >> 5, h = bh & 31;
    const float* acs = g_Acs + (size_t)bh * T_DIM;
    float atot = acs[T_DIM - 1];

    __shared__ float sx[32 * PX];
    __shared__ float sb[32 * PC];
    __shared__ float sd[32];

    int tid = threadIdx.x;
    int i2 = tid >> 4, j2 = tid & 15;
    float acc[4][8];
#pragma unroll
    for (int a = 0; a < 4; a++)
#pragma unroll
        for (int c2 = 0; c2 < 8; c2++) acc[a][c2] = 0.f;

    const int tspan = T_DIM / NSPLIT;   // 128
    const int t0base = split * tspan;
    for (int t0 = t0base; t0 < t0base + tspan; t0 += 32) {
        __syncthreads();
        for (int idx = tid; idx < 32 * 16; idx += 256) {
            int row = idx >> 4, q = idx & 15;
            *(float4*)(sx + row * PX + q * 4) =
                *(const float4*)(xg + ((size_t)((b * T_DIM + t0 + row) * H_DIM) + h) * P_DIM + q * 4);
        }
        for (int idx = tid; idx < 32 * 32; idx += 256) {
            int row = idx >> 5, q = idx & 31;
            *(float4*)(sb + row * PC + q * 4) =
                *(const float4*)(Bg + ((size_t)((b * T_DIM + t0 + row) * H_DIM) + h) * N_DIM + q * 4);
        }
        if (tid < 32) sd[tid] = __expf(atot - acs[t0 + tid]);
        __syncthreads();

        for (int tt = 0; tt < 32; ++tt) {
            float d = sd[tt];
            float a0[4], b0[8];
#pragma unroll
            for (int di = 0; di < 4; di++) a0[di] = sx[tt * PX + i2 + 16 * di] * d;
#pragma unroll
            for (int dj = 0; dj < 8; dj++) b0[dj] = sb[tt * PC + j2 + 16 * dj];
#pragma unroll
            for (int di = 0; di < 4; di++)
#pragma unroll
                for (int dj = 0; dj < 8; dj++)
                    acc[di][dj] += a0[di] * b0[dj];
        }
    }

    float* outp = g_part + ((size_t)split * BH + bh) * (P_DIM * N_DIM);
#pragma unroll
    for (int di = 0; di < 4; di++)
#pragma unroll
        for (int dj = 0; dj < 8; dj++)
            outp[(i2 + 16 * di) * N_DIM + (j2 + 16 * dj)] = acc[di][dj];
}

__global__ void reduce_kernel(float* __restrict__ out) {
    int idx = blockIdx.x * 256 + threadIdx.x;
    if (idx < FS_SIZE) {
        float s = 0.f;
#pragma unroll
        for (int sp = 0; sp < NSPLIT; ++sp)
            s += g_part[(size_t)sp * FS_SIZE + idx];
        out[Y_SIZE + idx] = s;
    }
}

// ---------------------------------------------------------------------------
extern "C" void kernel_launch(void* const* d_in, const int* in_sizes, int n_in,
                              void* d_out, int out_size) {
    const float* xg  = (const float*)d_in[0];
    const float* Ag  = (const float*)d_in[1];
    const float* Bg  = (const float*)d_in[2];
    const float* Cg  = (const float*)d_in[3];
    const float* Lm  = (const float*)d_in[4];
    const float* msf = (const float*)d_in[5];
    float* out = (float*)d_out;

    acs_kernel<<<BH, 1024>>>(Ag);

    int smem = (64 * PC * 2 + 64 * PX * 2 + 128) * (int)sizeof(float);  // ~100.5 KB
    cudaFuncSetAttribute(ssd_main_kernel,
                         cudaFuncAttributeMaxDynamicSharedMemorySize, smem);
    ssd_main_kernel<<<dim3(K_CH, BH), 256, smem>>>(xg, Bg, Cg, Lm, msf, out);

    state_kernel<<<dim3(NSPLIT, BH), 256>>>(xg, Bg);
    reduce_kernel<<<(FS_SIZE + 255) / 256, 256>>>(out);
}

// round 4
// speedup vs baseline: 1.5251x; 1.5251x over previous
#include <cuda_runtime.h>
#include <cuda_bf16.h>
#include <cstdint>

// Problem constants
#define B_DIM 2
#define T_DIM 1024
#define H_DIM 32
#define P_DIM 64
#define N_DIM 128
#define BH (B_DIM * H_DIM)
#define Y_SIZE (B_DIM * T_DIM * H_DIM * P_DIM)
#define FS_SIZE (BH * P_DIM * N_DIM)
#define NSPLIT 8

__device__ float g_Acs[BH * T_DIM];
__device__ float g_part[NSPLIT * FS_SIZE];

// ---------------- helpers ----------------
__device__ __forceinline__ uint32_t smem_u32(const void* p) {
    uint32_t a;
    asm("{ .reg .u64 t; cvta.to.shared.u64 t, %1; cvt.u32.u64 %0, t; }" : "=r"(a) : "l"(p));
    return a;
}
__device__ __forceinline__ void ldsm4(uint32_t& r0, uint32_t& r1, uint32_t& r2, uint32_t& r3, uint32_t addr) {
    asm volatile("ldmatrix.sync.aligned.m8n8.x4.shared.b16 {%0,%1,%2,%3}, [%4];"
                 : "=r"(r0), "=r"(r1), "=r"(r2), "=r"(r3) : "r"(addr));
}
__device__ __forceinline__ void mma16816(float* d, uint32_t a0, uint32_t a1, uint32_t a2, uint32_t a3,
                                         uint32_t b0, uint32_t b1) {
    asm volatile("mma.sync.aligned.m16n8k16.row.col.f32.bf16.bf16.f32 "
                 "{%0,%1,%2,%3}, {%4,%5,%6,%7}, {%8,%9}, {%0,%1,%2,%3};"
                 : "+f"(d[0]), "+f"(d[1]), "+f"(d[2]), "+f"(d[3])
                 : "r"(a0), "r"(a1), "r"(a2), "r"(a3), "r"(b0), "r"(b1));
}
// pack two fp32 -> bf16x2 (lo in low half)
__device__ __forceinline__ uint32_t pack_bf2(float lo, float hi) {
    uint32_t r;
    asm("cvt.rn.bf16x2.f32 %0, %1, %2;" : "=r"(r) : "f"(hi), "f"(lo));
    return r;
}
// split pair: hi-packed bits + residuals
__device__ __forceinline__ void split2(float x, float y, uint32_t& hibits, float& rx, float& ry) {
    __nv_bfloat16 h0 = __float2bfloat16_rn(x), h1 = __float2bfloat16_rn(y);
    hibits = (uint32_t)__bfloat16_as_ushort(h0) | ((uint32_t)__bfloat16_as_ushort(h1) << 16);
    rx = x - __bfloat162float(h0);
    ry = y - __bfloat162float(h1);
}

// SMEM layout (byte offsets from dynamic base). Pitches keep ldmatrix rows in
// distinct 16B bank-groups (272 = 17*16, 144 = 9*16).
#define PCH 272        // C / Bt row pitch (k=128 bf16 -> 256B + 16 pad)
#define PXH 144        // Xt row pitch (j=64 bf16 -> 128B + 16 pad)
#define O_ECOL 0                        // 64 floats
#define O_CHI  256
#define O_CLO  (O_CHI + 128 * PCH)      // 35072
#define O_BHI  (O_CLO + 128 * PCH)      // 69888
#define O_BLO  (O_BHI + 64 * PCH)       // 87296
#define O_XHI  (O_BLO + 64 * PCH)       // 104704
#define O_XLO  (O_XHI + 64 * PXH)       // 113920
#define SMEM_BYTES (O_XLO + 64 * PXH)   // 123136

// ---------------------------------------------------------------------------
// Kernel 1: per-(b,h) inclusive cumsum of A
// ---------------------------------------------------------------------------
__global__ void __launch_bounds__(1024) acs_kernel(const float* __restrict__ A) {
    int bh = blockIdx.x;
    int b = bh >> 5, h = bh & 31;
    __shared__ float buf[2][T_DIM];
    int t = threadIdx.x;
    buf[0][t] = A[(size_t)(b * T_DIM + t) * H_DIM + h];
    __syncthreads();
    int src = 0;
    for (int off = 1; off < T_DIM; off <<= 1) {
        float v = buf[src][t];
        if (t >= off) v += buf[src][t - off];
        buf[src ^ 1][t] = v;
        src ^= 1;
        __syncthreads();
    }
    g_Acs[bh * T_DIM + t] = buf[src][t];
}

// ---------------------------------------------------------------------------
// Main kernel: block = (r2, bh), 8 warps, warp owns 16 rows.
// Per col-tile c: S(16x64) = C·B^T (bf16x3 via mma.sync), fp32 mask epilogue
// in fragment registers, Y(16x64) += Ms·X (bf16x3), Y accumulated in regs.
// ---------------------------------------------------------------------------
__global__ void __launch_bounds__(256, 1)
ssd_mma_kernel(const float* __restrict__ xg, const float* __restrict__ Bg,
               const float* __restrict__ Cg, const float* __restrict__ Lm,
               const float* __restrict__ msfp, float* __restrict__ Yg)
{
    extern __shared__ char smb[];
    float* ecol = (float*)(smb + O_ECOL);
    const uint32_t sb = smem_u32(smb);

    const int r2 = 7 - (int)blockIdx.x;
    const int bh = blockIdx.y;
    const int b = bh >> 5, h = bh & 31;
    const int tid = threadIdx.x;
    const int w = tid >> 5, lane = tid & 31;
    const float msf = *msfp;
    const float* acs = g_Acs + (size_t)bh * T_DIM;
    const int ncols = 2 * r2 + 2;
    const int row0 = r2 * 128;

    // ---- load C (128x128) -> bf16 hi/lo tiles (row-major, pitch PCH) ----
    for (int idx = tid; idx < 128 * 32; idx += 256) {
        int row = idx >> 5, q = idx & 31;
        float4 v = *(const float4*)(Cg + ((size_t)((b * T_DIM + row0 + row) * H_DIM) + h) * N_DIM + q * 4);
        uint32_t h01, h23; float r0, r1, r2f, r3f;
        split2(v.x, v.y, h01, r0, r1);
        split2(v.z, v.w, h23, r2f, r3f);
        char* dst = smb + O_CHI + row * PCH + q * 8;
        *(uint2*)dst = make_uint2(h01, h23);
        *(uint2*)(dst + (O_CLO - O_CHI)) = make_uint2(pack_bf2(r0, r1), pack_bf2(r2f, r3f));
    }

    // lane geometry for ldmatrix / fragments
    const int g = lane >> 3;
    const int lrow = (g & 1) * 8 + (lane & 7);
    const int lcolB = ((g >> 1) * 8) * 2;   // byte offset of column-half
    const uint32_t aHi = sb + O_CHI + (w * 16 + lrow) * PCH + lcolB;
    const uint32_t aLo = aHi + (O_CLO - O_CHI);
    const uint32_t bHi = sb + O_BHI + lrow * PCH + lcolB;
    const uint32_t xHi = sb + O_XHI + lrow * PXH + lcolB;

    // fragment row indices (global)
    const int ig0 = row0 + w * 16 + (lane >> 2);
    const int ig1 = ig0 + 8;
    const float av0 = acs[ig0], av1 = acs[ig1];
    const int jmaxRow = row0 + w * 16 + 15;
    const float* lr0 = Lm + ((size_t)bh * T_DIM + ig0) * T_DIM;
    const float* lr1 = lr0 + 8 * T_DIM;

    float yacc[8][4];
#pragma unroll
    for (int i = 0; i < 8; i++)
#pragma unroll
        for (int e = 0; e < 4; e++) yacc[i][e] = 0.f;

    for (int c = 0; c < ncols; ++c) {
        __syncthreads();   // previous iteration's reads of sB/sX done

        // ---- load B tile (64 x 128) hi/lo ----
        for (int idx = tid; idx < 64 * 32; idx += 256) {
            int row = idx >> 5, q = idx & 31;
            float4 v = *(const float4*)(Bg + ((size_t)((b * T_DIM + c * 64 + row) * H_DIM) + h) * N_DIM + q * 4);
            uint32_t h01, h23; float r0, r1, r2f, r3f;
            split2(v.x, v.y, h01, r0, r1);
            split2(v.z, v.w, h23, r2f, r3f);
            char* dst = smb + O_BHI + row * PCH + q * 8;
            *(uint2*)dst = make_uint2(h01, h23);
            *(uint2*)(dst + (O_BLO - O_BHI)) = make_uint2(pack_bf2(r0, r1), pack_bf2(r2f, r3f));
        }
        // ---- load X tile transposed: Xt[p][j], hi/lo ----
        for (int idx = tid; idx < 64 * 16; idx += 256) {
            int j = idx >> 4, q = idx & 15;
            float4 v = *(const float4*)(xg + ((size_t)((b * T_DIM + c * 64 + j) * H_DIM) + h) * P_DIM + q * 4);
            const float* vp = (const float*)&v;
#pragma unroll
            for (int e = 0; e < 4; ++e) {
                int p = 4 * q + e;
                __nv_bfloat16 hh = __float2bfloat16_rn(vp[e]);
                float rr = vp[e] - __bfloat162float(hh);
                *(__nv_bfloat16*)(smb + O_XHI + p * PXH + j * 2) = hh;
                *(__nv_bfloat16*)(smb + O_XLO + p * PXH + j * 2) = __float2bfloat16_rn(rr);
            }
        }
        const float aj0 = acs[c * 64];
        if (tid < 64) ecol[tid] = __expf(aj0 - acs[c * 64 + tid]);
        __syncthreads();

        if (c * 64 > jmaxRow) continue;   // warp fully above diagonal (warp-uniform)

        // ================= Stage 1: S = C·B^T (3-pass bf16) =================
        float sacc[8][4];
#pragma unroll
        for (int i = 0; i < 8; i++)
#pragma unroll
            for (int e = 0; e < 4; e++) sacc[i][e] = 0.f;

#pragma unroll 1
        for (int pass = 0; pass < 3; ++pass) {
            uint32_t aB = (pass < 2) ? aHi : aLo;
            uint32_t bB = (pass == 1) ? (bHi + (O_BLO - O_BHI)) : bHi;
#pragma unroll
            for (int ks = 0; ks < 8; ++ks) {
                uint32_t a0, a1, a2, a3;
                ldsm4(a0, a1, a2, a3, aB + ks * 32);
#pragma unroll
                for (int nf2 = 0; nf2 < 4; ++nf2) {
                    uint32_t b0, b1, b2, b3;
                    ldsm4(b0, b1, b2, b3, bB + nf2 * (16 * PCH) + ks * 32);
                    mma16816(sacc[2 * nf2], a0, a1, a2, a3, b0, b2);
                    mma16816(sacc[2 * nf2 + 1], a0, a1, a2, a3, b1, b3);
                }
            }
        }

        // ================= Epilogue: mask + split to bf16 A-frags ===========
        const float erow0 = __expf(av0 - aj0);
        const float erow1 = __expf(av1 - aj0);
        uint32_t mhi[16], mlo[16];
        {
            const float* l0p = lr0 + c * 64;
            const float* l1p = lr1 + c * 64;
#pragma unroll
            for (int nf = 0; nf < 8; ++nf) {
                int jl = 8 * nf + (lane & 3) * 2;
                int jgv = c * 64 + jl;
                float2 L0 = *(const float2*)(l0p + jl);
                float2 L1 = *(const float2*)(l1p + jl);
                float ec0 = ecol[jl], ec1 = ecol[jl + 1];
                float f00 = (jgv     <= ig0) ? fmaf(msf, L0.x, erow0 * ec0) : 0.f;
                float f01 = (jgv + 1 <= ig0) ? fmaf(msf, L0.y, erow0 * ec1) : 0.f;
                float f10 = (jgv     <= ig1) ? fmaf(msf, L1.x, erow1 * ec0) : 0.f;
                float f11 = (jgv + 1 <= ig1) ? fmaf(msf, L1.y, erow1 * ec1) : 0.f;
                float m00 = sacc[nf][0] * f00, m01 = sacc[nf][1] * f01;
                float m10 = sacc[nf][2] * f10, m11 = sacc[nf][3] * f11;
                int ks = nf >> 1, part = nf & 1;
                int i0 = ks * 4 + part * 2;
                uint32_t hb; float rx, ry;
                split2(m00, m01, hb, rx, ry);
                mhi[i0] = hb; mlo[i0] = pack_bf2(rx, ry);
                split2(m10, m11, hb, rx, ry);
                mhi[i0 + 1] = hb; mlo[i0 + 1] = pack_bf2(rx, ry);
            }
        }

        // ================= Stage 2: Y += Ms·X (3-pass bf16) =================
        auto stage2 = [&](const uint32_t (&Ar)[16], uint32_t xB) {
#pragma unroll
            for (int ks = 0; ks < 4; ++ks) {
#pragma unroll
                for (int pf2 = 0; pf2 < 4; ++pf2) {
                    uint32_t b0, b1, b2, b3;
                    ldsm4(b0, b1, b2, b3, xB + pf2 * (16 * PXH) + ks * 32);
                    mma16816(yacc[2 * pf2],     Ar[4 * ks], Ar[4 * ks + 1], Ar[4 * ks + 2], Ar[4 * ks + 3], b0, b2);
                    mma16816(yacc[2 * pf2 + 1], Ar[4 * ks], Ar[4 * ks + 1], Ar[4 * ks + 2], Ar[4 * ks + 3], b1, b3);
                }
            }
        };
        stage2(mhi, xHi);
        stage2(mhi, xHi + (O_XLO - O_XHI));
        stage2(mlo, xHi);
    }

    // ---- write Y ----
    float* yr0 = Yg + ((size_t)((b * T_DIM + ig0) * H_DIM) + h) * P_DIM;
    float* yr1 = Yg + ((size_t)((b * T_DIM + ig1) * H_DIM) + h) * P_DIM;
#pragma unroll
    for (int pf = 0; pf < 8; ++pf) {
        int p0 = 8 * pf + (lane & 3) * 2;
        *(float2*)(yr0 + p0) = make_float2(yacc[pf][0], yacc[pf][1]);
        *(float2*)(yr1 + p0) = make_float2(yacc[pf][2], yacc[pf][3]);
    }
}

// ---------------------------------------------------------------------------
// final_state partials + reduce
// ---------------------------------------------------------------------------
#define PC 132
#define PX 68
__global__ void __launch_bounds__(256) state_kernel(
    const float* __restrict__ xg, const float* __restrict__ Bg)
{
    int split = blockIdx.x;
    int bh    = blockIdx.y;
    int b = bh >> 5, h = bh & 31;
    const float* acs = g_Acs + (size_t)bh * T_DIM;
    float atot = acs[T_DIM - 1];

    __shared__ float sx[32 * PX];
    __shared__ float sb[32 * PC];
    __shared__ float sd[32];

    int tid = threadIdx.x;
    int i2 = tid >> 4, j2 = tid & 15;
    float acc[4][8];
#pragma unroll
    for (int a = 0; a < 4; a++)
#pragma unroll
        for (int c2 = 0; c2 < 8; c2++) acc[a][c2] = 0.f;

    const int tspan = T_DIM / NSPLIT;
    const int t0base = split * tspan;
    for (int t0 = t0base; t0 < t0base + tspan; t0 += 32) {
        __syncthreads();
        for (int idx = tid; idx < 32 * 16; idx += 256) {
            int row = idx >> 4, q = idx & 15;
            *(float4*)(sx + row * PX + q * 4) =
                *(const float4*)(xg + ((size_t)((b * T_DIM + t0 + row) * H_DIM) + h) * P_DIM + q * 4);
        }
        for (int idx = tid; idx < 32 * 32; idx += 256) {
            int row = idx >> 5, q = idx & 31;
            *(float4*)(sb + row * PC + q * 4) =
                *(const float4*)(Bg + ((size_t)((b * T_DIM + t0 + row) * H_DIM) + h) * N_DIM + q * 4);
        }
        if (tid < 32) sd[tid] = __expf(atot - acs[t0 + tid]);
        __syncthreads();

        for (int tt = 0; tt < 32; ++tt) {
            float d = sd[tt];
            float a0[4], b0[8];
#pragma unroll
            for (int di = 0; di < 4; di++) a0[di] = sx[tt * PX + i2 + 16 * di] * d;
#pragma unroll
            for (int dj = 0; dj < 8; dj++) b0[dj] = sb[tt * PC + j2 + 16 * dj];
#pragma unroll
            for (int di = 0; di < 4; di++)
#pragma unroll
                for (int dj = 0; dj < 8; dj++)
                    acc[di][dj] += a0[di] * b0[dj];
        }
    }

    float* outp = g_part + ((size_t)split * BH + bh) * (P_DIM * N_DIM);
#pragma unroll
    for (int di = 0; di < 4; di++)
#pragma unroll
        for (int dj = 0; dj < 8; dj++)
            outp[(i2 + 16 * di) * N_DIM + (j2 + 16 * dj)] = acc[di][dj];
}

__global__ void reduce_kernel(float* __restrict__ out) {
    int idx = blockIdx.x * 256 + threadIdx.x;
    if (idx < FS_SIZE) {
        float s = 0.f;
#pragma unroll
        for (int sp = 0; sp < NSPLIT; ++sp)
            s += g_part[(size_t)sp * FS_SIZE + idx];
        out[Y_SIZE + idx] = s;
    }
}

// ---------------------------------------------------------------------------
extern "C" void kernel_launch(void* const* d_in, const int* in_sizes, int n_in,
                              void* d_out, int out_size) {
    const float* xg  = (const float*)d_in[0];
    const float* Ag  = (const float*)d_in[1];
    const float* Bg  = (const float*)d_in[2];
    const float* Cg  = (const float*)d_in[3];
    const float* Lm  = (const float*)d_in[4];
    const float* msf = (const float*)d_in[5];
    float* out = (float*)d_out;

    acs_kernel<<<BH, 1024>>>(Ag);

    cudaFuncSetAttribute(ssd_mma_kernel,
                         cudaFuncAttributeMaxDynamicSharedMemorySize, SMEM_BYTES);
    ssd_mma_kernel<<<dim3(8, BH), 256, SMEM_BYTES>>>(xg, Bg, Cg, Lm, msf, out);

    state_kernel<<<dim3(NSPLIT, BH), 256>>>(xg, Bg);
    reduce_kernel<<<(FS_SIZE + 255) / 256, 256>>>(out);
}

// round 5
// speedup vs baseline: 1.9431x; 1.2741x over previous
#include <cuda_runtime.h>
#include <cuda_bf16.h>
#include <cstdint>

// Problem constants
#define B_DIM 2
#define T_DIM 1024
#define H_DIM 32
#define P_DIM 64
#define N_DIM 128
#define BH (B_DIM * H_DIM)
#define Y_SIZE (B_DIM * T_DIM * H_DIM * P_DIM)
#define FS_SIZE (BH * P_DIM * N_DIM)
#define NSPLIT 8

__device__ float g_Acs[BH * T_DIM];
__device__ float g_part[NSPLIT * FS_SIZE];

// ---------------- helpers ----------------
__device__ __forceinline__ uint32_t smem_u32(const void* p) {
    uint32_t a;
    asm("{ .reg .u64 t; cvta.to.shared.u64 t, %1; cvt.u32.u64 %0, t; }" : "=r"(a) : "l"(p));
    return a;
}
__device__ __forceinline__ void ldsm4(uint32_t& r0, uint32_t& r1, uint32_t& r2, uint32_t& r3, uint32_t addr) {
    asm volatile("ldmatrix.sync.aligned.m8n8.x4.shared.b16 {%0,%1,%2,%3}, [%4];"
                 : "=r"(r0), "=r"(r1), "=r"(r2), "=r"(r3) : "r"(addr));
}
__device__ __forceinline__ void mma16816(float* d, uint32_t a0, uint32_t a1, uint32_t a2, uint32_t a3,
                                         uint32_t b0, uint32_t b1) {
    asm volatile("mma.sync.aligned.m16n8k16.row.col.f32.bf16.bf16.f32 "
                 "{%0,%1,%2,%3}, {%4,%5,%6,%7}, {%8,%9}, {%0,%1,%2,%3};"
                 : "+f"(d[0]), "+f"(d[1]), "+f"(d[2]), "+f"(d[3])
                 : "r"(a0), "r"(a1), "r"(a2), "r"(a3), "r"(b0), "r"(b1));
}
__device__ __forceinline__ uint32_t pack_bf2(float lo, float hi) {
    uint32_t r;
    asm("cvt.rn.bf16x2.f32 %0, %1, %2;" : "=r"(r) : "f"(hi), "f"(lo));
    return r;
}
__device__ __forceinline__ void split2(float x, float y, uint32_t& hibits, float& rx, float& ry) {
    __nv_bfloat16 h0 = __float2bfloat16_rn(x), h1 = __float2bfloat16_rn(y);
    hibits = (uint32_t)__bfloat16_as_ushort(h0) | ((uint32_t)__bfloat16_as_ushort(h1) << 16);
    rx = x - __bfloat162float(h0);
    ry = y - __bfloat162float(h1);
}

// SMEM layout (byte offsets). Pitches keep ldmatrix rows in distinct 16B groups.
#define PCH 272
#define PXH 144
#define O_ECOL 0                              // 2 x 64 floats (double-buffered)
#define O_CHI  1024
#define O_CLO  (O_CHI + 128 * PCH)            // 35840
#define O_B    (O_CLO + 128 * PCH)            // 70656 ; per buf 34816 (hi 0 / lo 17408)
#define O_X    (O_B + 2 * 34816)              // 140288; per buf 18432 (hi 0 / lo 9216)
#define SMEM_BYTES (O_X + 2 * 18432)          // 177152

#define THREADS 512

// ---------------------------------------------------------------------------
__global__ void __launch_bounds__(1024) acs_kernel(const float* __restrict__ A) {
    int bh = blockIdx.x;
    int b = bh >> 5, h = bh & 31;
    __shared__ float buf[2][T_DIM];
    int t = threadIdx.x;
    buf[0][t] = A[(size_t)(b * T_DIM + t) * H_DIM + h];
    __syncthreads();
    int src = 0;
    for (int off = 1; off < T_DIM; off <<= 1) {
        float v = buf[src][t];
        if (t >= off) v += buf[src][t - off];
        buf[src ^ 1][t] = v;
        src ^= 1;
        __syncthreads();
    }
    g_Acs[bh * T_DIM + t] = buf[src][t];
}

// ---------------------------------------------------------------------------
// Main kernel: block = (r2, bh), 16 warps. Warp pair (w, w+8) shares rows
// [wr*16, wr*16+16), splits the 64 j-columns (jh = w>>3). Double-buffered
// smem tiles, register-pipelined LDGs, Lm prefetch into registers.
// ---------------------------------------------------------------------------
__global__ void __launch_bounds__(THREADS, 1)
ssd_mma_kernel(const float* __restrict__ xg, const float* __restrict__ Bg,
               const float* __restrict__ Cg, const float* __restrict__ Lm,
               const float* __restrict__ msfp, float* __restrict__ Yg)
{
    extern __shared__ char smb[];
    float* ecolb = (float*)(smb + O_ECOL);
    const uint32_t sb = smem_u32(smb);

    const int r2 = 7 - (int)blockIdx.x;
    const int bh = blockIdx.y;
    const int b = bh >> 5, h = bh & 31;
    const int tid = threadIdx.x;
    const int w = tid >> 5, lane = tid & 31;
    const int wr = w & 7;            // row group
    const int jh = w >> 3;           // j half (0/1)
    const int joff = jh * 32;
    const float msf = *msfp;
    const float* acs = g_Acs + (size_t)bh * T_DIM;
    const int ncols = 2 * r2 + 2;
    const int row0 = r2 * 128;

    // ---- load + convert C (128x128) once ----
    for (int u = 0; u < 8; ++u) {
        int idx = tid + u * THREADS;
        int row = idx >> 5, q = idx & 31;
        float4 v = *(const float4*)(Cg + ((size_t)((b * T_DIM + row0 + row) * H_DIM) + h) * N_DIM + q * 4);
        uint32_t h01, h23; float r0, r1, r2f, r3f;
        split2(v.x, v.y, h01, r0, r1);
        split2(v.z, v.w, h23, r2f, r3f);
        char* dst = smb + O_CHI + row * PCH + q * 8;
        *(uint2*)dst = make_uint2(h01, h23);
        *(uint2*)(dst + (O_CLO - O_CHI)) = make_uint2(pack_bf2(r0, r1), pack_bf2(r2f, r3f));
    }

    // lane geometry
    const int g = lane >> 3;
    const int lrow = (g & 1) * 8 + (lane & 7);
    const int lcolB = (g >> 1) * 16;   // byte offset of k-half
    const uint32_t aHi = sb + O_CHI + (wr * 16 + lrow) * PCH + lcolB;
    const uint32_t aLo = aHi + (uint32_t)(O_CLO - O_CHI);

    const int ig0 = row0 + wr * 16 + (lane >> 2);
    const int ig1 = ig0 + 8;
    const float av0 = acs[ig0], av1 = acs[ig1];
    const int jmaxRow = row0 + wr * 16 + 15;
    const float* lr0 = Lm + ((size_t)bh * T_DIM + ig0) * T_DIM;
    const float* lr1 = lr0 + 8 * T_DIM;

    float yacc[8][4];
#pragma unroll
    for (int i = 0; i < 8; i++)
#pragma unroll
        for (int e = 0; e < 4; e++) yacc[i][e] = 0.f;

    // ---- staging registers ----
    float4 bR[4], xR[2];
    auto loadBX = [&](int c) {
#pragma unroll
        for (int u = 0; u < 4; ++u) {
            int idx = tid + u * THREADS;
            int row = idx >> 5, q = idx & 31;
            bR[u] = *(const float4*)(Bg + ((size_t)((b * T_DIM + c * 64 + row) * H_DIM) + h) * N_DIM + q * 4);
        }
#pragma unroll
        for (int u = 0; u < 2; ++u) {
            int idx = tid + u * THREADS;
            int j = idx >> 4, q = idx & 15;
            xR[u] = *(const float4*)(xg + ((size_t)((b * T_DIM + c * 64 + j) * H_DIM) + h) * P_DIM + q * 4);
        }
    };
    auto storeBX = [&](int nb) {
        char* bbase = smb + O_B + nb * 34816;
#pragma unroll
        for (int u = 0; u < 4; ++u) {
            int idx = tid + u * THREADS;
            int row = idx >> 5, q = idx & 31;
            uint32_t h01, h23; float r0, r1, r2f, r3f;
            split2(bR[u].x, bR[u].y, h01, r0, r1);
            split2(bR[u].z, bR[u].w, h23, r2f, r3f);
            char* dst = bbase + row * PCH + q * 8;
            *(uint2*)dst = make_uint2(h01, h23);
            *(uint2*)(dst + 17408) = make_uint2(pack_bf2(r0, r1), pack_bf2(r2f, r3f));
        }
        char* xbase = smb + O_X + nb * 18432;
#pragma unroll
        for (int u = 0; u < 2; ++u) {
            int idx = tid + u * THREADS;
            int j = idx >> 4, q = idx & 15;
            const float* vp = (const float*)&xR[u];
#pragma unroll
            for (int e = 0; e < 4; ++e) {
                int p = 4 * q + e;
                __nv_bfloat16 hh = __float2bfloat16_rn(vp[e]);
                float rr = vp[e] - __bfloat162float(hh);
                *(__nv_bfloat16*)(xbase + p * PXH + j * 2) = hh;
                *(__nv_bfloat16*)(xbase + 9216 + p * PXH + j * 2) = __float2bfloat16_rn(rr);
            }
        }
    };

    // ---- prologue: fill buffer 0 ----
    loadBX(0);
    float ecv = 0.f;
    if (tid < 64) ecv = __expf(acs[0] - acs[tid]);
    storeBX(0);
    if (tid < 64) ecolb[tid] = ecv;
    __syncthreads();

    for (int c = 0; c < ncols; ++c) {
        const int cur = c & 1;
        const bool more = (c + 1 < ncols);
        if (more) loadBX(c + 1);                 // LDG issue, consumed later
        float ecn = 0.f;
        if (more && tid < 64) ecn = __expf(__ldg(acs + (c + 1) * 64) - __ldg(acs + (c + 1) * 64 + tid));

        const bool active = (c * 64 <= jmaxRow);
        if (active) {
            // ---- Lm prefetch (registers) ----
            float2 L0[4], L1[4];
            const float* l0p = lr0 + c * 64 + joff;
            const float* l1p = lr1 + c * 64 + joff;
#pragma unroll
            for (int nf = 0; nf < 4; ++nf) {
                int jl = 8 * nf + (lane & 3) * 2;
                L0[nf] = *(const float2*)(l0p + jl);
                L1[nf] = *(const float2*)(l1p + jl);
            }
            const float aj0 = __ldg(acs + c * 64);

            // ---- Stage 1: S(16x32) = C·B^T, 3-pass bf16 ----
            float sacc[4][4];
#pragma unroll
            for (int i = 0; i < 4; i++)
#pragma unroll
                for (int e = 0; e < 4; e++) sacc[i][e] = 0.f;

            const uint32_t bBase = sb + O_B + cur * 34816 + (joff + lrow) * PCH + lcolB;
#pragma unroll 1
            for (int pass = 0; pass < 3; ++pass) {
                uint32_t aB = (pass < 2) ? aHi : aLo;
                uint32_t bB = (pass == 1) ? (bBase + 17408) : bBase;
#pragma unroll
                for (int ks = 0; ks < 8; ++ks) {
                    uint32_t a0, a1, a2, a3;
                    ldsm4(a0, a1, a2, a3, aB + ks * 32);
#pragma unroll
                    for (int nf2 = 0; nf2 < 2; ++nf2) {
                        uint32_t b0, b1, b2, b3;
                        ldsm4(b0, b1, b2, b3, bB + nf2 * (16 * PCH) + ks * 32);
                        mma16816(sacc[2 * nf2],     a0, a1, a2, a3, b0, b2);
                        mma16816(sacc[2 * nf2 + 1], a0, a1, a2, a3, b1, b3);
                    }
                }
            }

            // ---- Epilogue: mask + split into A-fragments ----
            const float erow0 = __expf(av0 - aj0);
            const float erow1 = __expf(av1 - aj0);
            const float* ecol = ecolb + cur * 64;
            uint32_t mhi[8], mlo[8];
#pragma unroll
            for (int nf = 0; nf < 4; ++nf) {
                int jl = joff + 8 * nf + (lane & 3) * 2;
                int jgv = c * 64 + jl;
                float2 ec = *(const float2*)(ecol + jl);
                float f00 = (jgv     <= ig0) ? fmaf(msf, L0[nf].x, erow0 * ec.x) : 0.f;
                float f01 = (jgv + 1 <= ig0) ? fmaf(msf, L0[nf].y, erow0 * ec.y) : 0.f;
                float f10 = (jgv     <= ig1) ? fmaf(msf, L1[nf].x, erow1 * ec.x) : 0.f;
                float f11 = (jgv + 1 <= ig1) ? fmaf(msf, L1[nf].y, erow1 * ec.y) : 0.f;
                float m00 = sacc[nf][0] * f00, m01 = sacc[nf][1] * f01;
                float m10 = sacc[nf][2] * f10, m11 = sacc[nf][3] * f11;
                int ks = nf >> 1, part = nf & 1;
                int i0 = ks * 4 + part * 2;
                uint32_t hb; float rx, ry;
                split2(m00, m01, hb, rx, ry);
                mhi[i0] = hb; mlo[i0] = pack_bf2(rx, ry);
                split2(m10, m11, hb, rx, ry);
                mhi[i0 + 1] = hb; mlo[i0 + 1] = pack_bf2(rx, ry);
            }

            // ---- Stage 2: Y += Ms·X (K = warp's 32 j), 3-pass ----
            const uint32_t xBase = sb + O_X + cur * 18432 + lrow * PXH + joff * 2 + lcolB;
#pragma unroll 1
            for (int pass = 0; pass < 3; ++pass) {
                const uint32_t* Ar = (pass < 2) ? mhi : mlo;
                uint32_t xB = (pass == 1) ? (xBase + 9216) : xBase;
#pragma unroll
                for (int ks = 0; ks < 2; ++ks) {
#pragma unroll
                    for (int pf2 = 0; pf2 < 4; ++pf2) {
                        uint32_t b0, b1, b2, b3;
                        ldsm4(b0, b1, b2, b3, xB + pf2 * (16 * PXH) + ks * 32);
                        mma16816(yacc[2 * pf2],     Ar[4 * ks], Ar[4 * ks + 1], Ar[4 * ks + 2], Ar[4 * ks + 3], b0, b2);
                        mma16816(yacc[2 * pf2 + 1], Ar[4 * ks], Ar[4 * ks + 1], Ar[4 * ks + 2], Ar[4 * ks + 3], b1, b3);
                    }
                }
            }
        }

        if (more) {
            storeBX((c + 1) & 1);
            if (tid < 64) ecolb[((c + 1) & 1) * 64 + tid] = ecn;
        }
        __syncthreads();
    }

    // ---- reduce warp pairs (w, w+8) and write Y ----
    float* stag = (float*)(smb + O_B);
    if (w >= 8) {
        float* d = stag + ((w - 8) * 32 + lane) * 32;
#pragma unroll
        for (int i = 0; i < 8; ++i)
#pragma unroll
            for (int e = 0; e < 4; ++e) d[i * 4 + e] = yacc[i][e];
    }
    __syncthreads();
    if (w < 8) {
        const float* s = stag + (w * 32 + lane) * 32;
        float* yr0 = Yg + ((size_t)((b * T_DIM + ig0) * H_DIM) + h) * P_DIM;
        float* yr1 = Yg + ((size_t)((b * T_DIM + ig1) * H_DIM) + h) * P_DIM;
#pragma unroll
        for (int pf = 0; pf < 8; ++pf) {
            int p0 = 8 * pf + (lane & 3) * 2;
            *(float2*)(yr0 + p0) = make_float2(yacc[pf][0] + s[pf * 4 + 0], yacc[pf][1] + s[pf * 4 + 1]);
            *(float2*)(yr1 + p0) = make_float2(yacc[pf][2] + s[pf * 4 + 2], yacc[pf][3] + s[pf * 4 + 3]);
        }
    }
}

// ---------------------------------------------------------------------------
// final_state partials + reduce
// ---------------------------------------------------------------------------
#define PC 132
#define PX 68
__global__ void __launch_bounds__(256) state_kernel(
    const float* __restrict__ xg, const float* __restrict__ Bg)
{
    int split = blockIdx.x;
    int bh    = blockIdx.y;
    int b = bh >> 5, h = bh & 31;
    const float* acs = g_Acs + (size_t)bh * T_DIM;
    float atot = acs[T_DIM - 1];

    __shared__ float sx[32 * PX];
    __shared__ float sb[32 * PC];
    __shared__ float sd[32];

    int tid = threadIdx.x;
    int i2 = tid >> 4, j2 = tid & 15;
    float acc[4][8];
#pragma unroll
    for (int a = 0; a < 4; a++)
#pragma unroll
        for (int c2 = 0; c2 < 8; c2++) acc[a][c2] = 0.f;

    const int tspan = T_DIM / NSPLIT;
    const int t0base = split * tspan;
    for (int t0 = t0base; t0 < t0base + tspan; t0 += 32) {
        __syncthreads();
        for (int idx = tid; idx < 32 * 16; idx += 256) {
            int row = idx >> 4, q = idx & 15;
            *(float4*)(sx + row * PX + q * 4) =
                *(const float4*)(xg + ((size_t)((b * T_DIM + t0 + row) * H_DIM) + h) * P_DIM + q * 4);
        }
        for (int idx = tid; idx < 32 * 32; idx += 256) {
            int row = idx >> 5, q = idx & 31;
            *(float4*)(sb + row * PC + q * 4) =
                *(const float4*)(Bg + ((size_t)((b * T_DIM + t0 + row) * H_DIM) + h) * N_DIM + q * 4);
        }
        if (tid < 32) sd[tid] = __expf(atot - acs[t0 + tid]);
        __syncthreads();

        for (int tt = 0; tt < 32; ++tt) {
            float d = sd[tt];
            float a0[4], b0[8];
#pragma unroll
            for (int di = 0; di < 4; di++) a0[di] = sx[tt * PX + i2 + 16 * di] * d;
#pragma unroll
            for (int dj = 0; dj < 8; dj++) b0[dj] = sb[tt * PC + j2 + 16 * dj];
#pragma unroll
            for (int di = 0; di < 4; di++)
#pragma unroll
                for (int dj = 0; dj < 8; dj++)
                    acc[di][dj] += a0[di] * b0[dj];
        }
    }

    float* outp = g_part + ((size_t)split * BH + bh) * (P_DIM * N_DIM);
#pragma unroll
    for (int di = 0; di < 4; di++)
#pragma unroll
        for (int dj = 0; dj < 8; dj++)
            outp[(i2 + 16 * di) * N_DIM + (j2 + 16 * dj)] = acc[di][dj];
}

__global__ void reduce_kernel(float* __restrict__ out) {
    int idx = blockIdx.x * 256 + threadIdx.x;
    if (idx < FS_SIZE) {
        float s = 0.f;
#pragma unroll
        for (int sp = 0; sp < NSPLIT; ++sp)
            s += g_part[(size_t)sp * FS_SIZE + idx];
        out[Y_SIZE + idx] = s;
    }
}

// ---------------------------------------------------------------------------
extern "C" void kernel_launch(void* const* d_in, const int* in_sizes, int n_in,
                              void* d_out, int out_size) {
    const float* xg  = (const float*)d_in[0];
    const float* Ag  = (const float*)d_in[1];
    const float* Bg  = (const float*)d_in[2];
    const float* Cg  = (const float*)d_in[3];
    const float* Lm  = (const float*)d_in[4];
    const float* msf = (const float*)d_in[5];
    float* out = (float*)d_out;

    acs_kernel<<<BH, 1024>>>(Ag);

    cudaFuncSetAttribute(ssd_mma_kernel,
                         cudaFuncAttributeMaxDynamicSharedMemorySize, SMEM_BYTES);
    ssd_mma_kernel<<<dim3(8, BH), THREADS, SMEM_BYTES>>>(xg, Bg, Cg, Lm, msf, out);

    state_kernel<<<dim3(NSPLIT, BH), 256>>>(xg, Bg);
    reduce_kernel<<<(FS_SIZE + 255) / 256, 256>>>(out);
}

// round 6
// speedup vs baseline: 2.9407x; 1.5134x over previous
#include <cuda_runtime.h>
#include <cuda_fp16.h>
#include <cstdint>

// Problem constants
#define B_DIM 2
#define T_DIM 1024
#define H_DIM 32
#define P_DIM 64
#define N_DIM 128
#define BH (B_DIM * H_DIM)
#define Y_SIZE (B_DIM * T_DIM * H_DIM * P_DIM)
#define FS_SIZE (BH * P_DIM * N_DIM)
#define NSPLIT 8

__device__ float g_Acs[BH * T_DIM];
__device__ float g_part[NSPLIT * FS_SIZE];

// ---------------- helpers ----------------
__device__ __forceinline__ uint32_t smem_u32(const void* p) {
    uint32_t a;
    asm("{ .reg .u64 t; cvta.to.shared.u64 t, %1; cvt.u32.u64 %0, t; }" : "=r"(a) : "l"(p));
    return a;
}
__device__ __forceinline__ void ldsm4(uint32_t& r0, uint32_t& r1, uint32_t& r2, uint32_t& r3, uint32_t addr) {
    asm volatile("ldmatrix.sync.aligned.m8n8.x4.shared.b16 {%0,%1,%2,%3}, [%4];"
                 : "=r"(r0), "=r"(r1), "=r"(r2), "=r"(r3) : "r"(addr));
}
__device__ __forceinline__ void mma16816(float* d, uint32_t a0, uint32_t a1, uint32_t a2, uint32_t a3,
                                         uint32_t b0, uint32_t b1) {
    asm volatile("mma.sync.aligned.m16n8k16.row.col.f32.f16.f16.f32 "
                 "{%0,%1,%2,%3}, {%4,%5,%6,%7}, {%8,%9}, {%0,%1,%2,%3};"
                 : "+f"(d[0]), "+f"(d[1]), "+f"(d[2]), "+f"(d[3])
                 : "r"(a0), "r"(a1), "r"(a2), "r"(a3), "r"(b0), "r"(b1));
}
// pack two fp32 -> f16x2 (x in low half)
__device__ __forceinline__ uint32_t pack_h2(float x, float y) {
    uint32_t r;
    asm("cvt.rn.f16x2.f32 %0, %1, %2;" : "=r"(r) : "f"(y), "f"(x));
    return r;
}
// split pair into fp16 hi bits + float residuals
__device__ __forceinline__ void split2h(float x, float y, uint32_t& hibits, float& rx, float& ry) {
    __half h0 = __float2half_rn(x), h1 = __float2half_rn(y);
    hibits = (uint32_t)__half_as_ushort(h0) | ((uint32_t)__half_as_ushort(h1) << 16);
    rx = x - __half2float(h0);
    ry = y - __half2float(h1);
}

// SMEM layout. Pitches keep ldmatrix rows in distinct 16B groups.
#define PCH 272
#define PXH 144
#define O_ECOL 0                              // 2 x 64 floats
#define O_CHI  1024
#define O_CLO  (O_CHI + 128 * PCH)            // 35840
#define O_B    (O_CLO + 128 * PCH)            // 70656 ; 2 bufs x 17408 (hi only)
#define O_X    (O_B + 2 * 17408)              // 105472; 2 bufs x 9216 (hi only)
#define SMEM_BYTES (O_X + 2 * 9216)           // 123904

#define THREADS 512

// ---------------------------------------------------------------------------
__global__ void __launch_bounds__(1024) acs_kernel(const float* __restrict__ A) {
    int bh = blockIdx.x;
    int b = bh >> 5, h = bh & 31;
    __shared__ float buf[2][T_DIM];
    int t = threadIdx.x;
    buf[0][t] = A[(size_t)(b * T_DIM + t) * H_DIM + h];
    __syncthreads();
    int src = 0;
    for (int off = 1; off < T_DIM; off <<= 1) {
        float v = buf[src][t];
        if (t >= off) v += buf[src][t - off];
        buf[src ^ 1][t] = v;
        src ^= 1;
        __syncthreads();
    }
    g_Acs[bh * T_DIM + t] = buf[src][t];
}

// ---------------------------------------------------------------------------
// Main kernel: block = (r2, bh), 16 warps. Warp pair (w, w+8) shares 16 rows,
// splits the 64 j-columns. fp16 2-pass split (A-side hi+lo, B-side rounded
// once, B-fragments shared across both passes). Double-buffered B/X tiles.
// ---------------------------------------------------------------------------
__global__ void __launch_bounds__(THREADS, 1)
ssd_mma_kernel(const float* __restrict__ xg, const float* __restrict__ Bg,
               const float* __restrict__ Cg, const float* __restrict__ Lm,
               const float* __restrict__ msfp, float* __restrict__ Yg)
{
    extern __shared__ char smb[];
    float* ecolb = (float*)(smb + O_ECOL);
    const uint32_t sb = smem_u32(smb);

    const int r2 = 7 - (int)blockIdx.x;
    const int bh = blockIdx.y;
    const int b = bh >> 5, h = bh & 31;
    const int tid = threadIdx.x;
    const int w = tid >> 5, lane = tid & 31;
    const int wr = w & 7;
    const int joff = (w >> 3) * 32;
    const float msf = *msfp;
    const float* acs = g_Acs + (size_t)bh * T_DIM;
    const int ncols = 2 * r2 + 2;
    const int row0 = r2 * 128;

    // ---- load + split C (128x128) once: Chi/Clo fp16 tiles ----
    for (int u = 0; u < 8; ++u) {
        int idx = tid + u * THREADS;
        int row = idx >> 5, q = idx & 31;
        float4 v = *(const float4*)(Cg + ((size_t)((b * T_DIM + row0 + row) * H_DIM) + h) * N_DIM + q * 4);
        uint32_t h01, h23; float r0, r1, r2f, r3f;
        split2h(v.x, v.y, h01, r0, r1);
        split2h(v.z, v.w, h23, r2f, r3f);
        char* dst = smb + O_CHI + row * PCH + q * 8;
        *(uint2*)dst = make_uint2(h01, h23);
        *(uint2*)(dst + (O_CLO - O_CHI)) = make_uint2(pack_h2(r0, r1), pack_h2(r2f, r3f));
    }

    // lane geometry
    const int g = lane >> 3;
    const int lrow = (g & 1) * 8 + (lane & 7);
    const int lcolB = (g >> 1) * 16;
    const uint32_t aHi = sb + O_CHI + (wr * 16 + lrow) * PCH + lcolB;
    const uint32_t aLo = aHi + (uint32_t)(O_CLO - O_CHI);

    const int ig0 = row0 + wr * 16 + (lane >> 2);
    const int ig1 = ig0 + 8;
    const float av0 = acs[ig0], av1 = acs[ig1];
    const int jmaxRow = row0 + wr * 16 + 15;
    const float* lr0 = Lm + ((size_t)bh * T_DIM + ig0) * T_DIM;
    const float* lr1 = lr0 + 8 * T_DIM;

    float yacc[8][4];
#pragma unroll
    for (int i = 0; i < 8; i++)
#pragma unroll
        for (int e = 0; e < 4; e++) yacc[i][e] = 0.f;

    // ---- staging registers ----
    float4 bR[4], xR[2];
    auto loadBX = [&](int c) {
#pragma unroll
        for (int u = 0; u < 4; ++u) {
            int idx = tid + u * THREADS;
            int row = idx >> 5, q = idx & 31;
            bR[u] = *(const float4*)(Bg + ((size_t)((b * T_DIM + c * 64 + row) * H_DIM) + h) * N_DIM + q * 4);
        }
#pragma unroll
        for (int u = 0; u < 2; ++u) {
            int idx = tid + u * THREADS;
            int j = idx >> 4, q = idx & 15;
            xR[u] = *(const float4*)(xg + ((size_t)((b * T_DIM + c * 64 + j) * H_DIM) + h) * P_DIM + q * 4);
        }
    };
    auto storeBX = [&](int nb) {
        char* bbase = smb + O_B + nb * 17408;
#pragma unroll
        for (int u = 0; u < 4; ++u) {
            int idx = tid + u * THREADS;
            int row = idx >> 5, q = idx & 31;
            *(uint2*)(bbase + row * PCH + q * 8) =
                make_uint2(pack_h2(bR[u].x, bR[u].y), pack_h2(bR[u].z, bR[u].w));
        }
        char* xbase = smb + O_X + nb * 9216;
#pragma unroll
        for (int u = 0; u < 2; ++u) {
            int idx = tid + u * THREADS;
            int j = idx >> 4, q = idx & 15;
            const float* vp = (const float*)&xR[u];
#pragma unroll
            for (int e = 0; e < 4; ++e) {
                int p = 4 * q + e;
                *(__half*)(xbase + p * PXH + j * 2) = __float2half_rn(vp[e]);
            }
        }
    };

    // ---- prologue ----
    loadBX(0);
    float ecv = 0.f;
    if (tid < 64) ecv = __expf(acs[0] - acs[tid]);
    storeBX(0);
    if (tid < 64) ecolb[tid] = ecv;
    __syncthreads();

    for (int c = 0; c < ncols; ++c) {
        const int cur = c & 1;
        const bool more = (c + 1 < ncols);
        if (more) loadBX(c + 1);
        float ecn = 0.f;
        if (more && tid < 64) ecn = __expf(__ldg(acs + (c + 1) * 64) - __ldg(acs + (c + 1) * 64 + tid));

        const bool active = (c * 64 <= jmaxRow);
        if (active) {
            // ---- Lm prefetch ----
            float2 L0[4], L1[4];
            const float* l0p = lr0 + c * 64 + joff;
            const float* l1p = lr1 + c * 64 + joff;
#pragma unroll
            for (int nf = 0; nf < 4; ++nf) {
                int jl = 8 * nf + (lane & 3) * 2;
                L0[nf] = *(const float2*)(l0p + jl);
                L1[nf] = *(const float2*)(l1p + jl);
            }
            const float aj0 = __ldg(acs + c * 64);

            // ---- Stage 1: S(16x32) = (Chi+Clo)·Bh^T, shared B frags ----
            float sacc[4][4];
#pragma unroll
            for (int i = 0; i < 4; i++)
#pragma unroll
                for (int e = 0; e < 4; e++) sacc[i][e] = 0.f;

            const uint32_t bBase = sb + O_B + cur * 17408 + (joff + lrow) * PCH + lcolB;
#pragma unroll
            for (int ks = 0; ks < 8; ++ks) {
                uint32_t ah0, ah1, ah2, ah3, al0, al1, al2, al3;
                ldsm4(ah0, ah1, ah2, ah3, aHi + ks * 32);
                ldsm4(al0, al1, al2, al3, aLo + ks * 32);
#pragma unroll
                for (int nf2 = 0; nf2 < 2; ++nf2) {
                    uint32_t b0, b1, b2, b3;
                    ldsm4(b0, b1, b2, b3, bBase + nf2 * (16 * PCH) + ks * 32);
                    mma16816(sacc[2 * nf2],     ah0, ah1, ah2, ah3, b0, b2);
                    mma16816(sacc[2 * nf2 + 1], ah0, ah1, ah2, ah3, b1, b3);
                    mma16816(sacc[2 * nf2],     al0, al1, al2, al3, b0, b2);
                    mma16816(sacc[2 * nf2 + 1], al0, al1, al2, al3, b1, b3);
                }
            }

            // ---- Epilogue: mask + split Ms into fp16 hi/lo A-frags ----
            const float erow0 = __expf(av0 - aj0);
            const float erow1 = __expf(av1 - aj0);
            const float* ecol = ecolb + cur * 64;
            uint32_t mhi[8], mlo[8];
#pragma unroll
            for (int nf = 0; nf < 4; ++nf) {
                int jl = joff + 8 * nf + (lane & 3) * 2;
                int jgv = c * 64 + jl;
                float2 ec = *(const float2*)(ecol + jl);
                float f00 = (jgv     <= ig0) ? fmaf(msf, L0[nf].x, erow0 * ec.x) : 0.f;
                float f01 = (jgv + 1 <= ig0) ? fmaf(msf, L0[nf].y, erow0 * ec.y) : 0.f;
                float f10 = (jgv     <= ig1) ? fmaf(msf, L1[nf].x, erow1 * ec.x) : 0.f;
                float f11 = (jgv + 1 <= ig1) ? fmaf(msf, L1[nf].y, erow1 * ec.y) : 0.f;
                float m00 = sacc[nf][0] * f00, m01 = sacc[nf][1] * f01;
                float m10 = sacc[nf][2] * f10, m11 = sacc[nf][3] * f11;
                int ks = nf >> 1, part = nf & 1;
                int i0 = ks * 4 + part * 2;
                uint32_t hb; float rx, ry;
                split2h(m00, m01, hb, rx, ry);
                mhi[i0] = hb; mlo[i0] = pack_h2(rx, ry);
                split2h(m10, m11, hb, rx, ry);
                mhi[i0 + 1] = hb; mlo[i0 + 1] = pack_h2(rx, ry);
            }

            // ---- Stage 2: Y += (Mh+Ml)·Xh, shared X frags ----
            const uint32_t xBase = sb + O_X + cur * 9216 + lrow * PXH + joff * 2 + lcolB;
#pragma unroll
            for (int ks = 0; ks < 2; ++ks) {
#pragma unroll
                for (int pf2 = 0; pf2 < 4; ++pf2) {
                    uint32_t b0, b1, b2, b3;
                    ldsm4(b0, b1, b2, b3, xBase + pf2 * (16 * PXH) + ks * 32);
                    mma16816(yacc[2 * pf2],     mhi[4 * ks], mhi[4 * ks + 1], mhi[4 * ks + 2], mhi[4 * ks + 3], b0, b2);
                    mma16816(yacc[2 * pf2 + 1], mhi[4 * ks], mhi[4 * ks + 1], mhi[4 * ks + 2], mhi[4 * ks + 3], b1, b3);
                    mma16816(yacc[2 * pf2],     mlo[4 * ks], mlo[4 * ks + 1], mlo[4 * ks + 2], mlo[4 * ks + 3], b0, b2);
                    mma16816(yacc[2 * pf2 + 1], mlo[4 * ks], mlo[4 * ks + 1], mlo[4 * ks + 2], mlo[4 * ks + 3], b1, b3);
                }
            }
        }

        if (more) {
            storeBX((c + 1) & 1);
            if (tid < 64) ecolb[((c + 1) & 1) * 64 + tid] = ecn;
        }
        __syncthreads();
    }

    // ---- reduce warp pairs (w, w+8) and write Y ----
    float* stag = (float*)(smb + O_B);
    if (w >= 8) {
        float* d = stag + ((w - 8) * 32 + lane) * 32;
#pragma unroll
        for (int i = 0; i < 8; ++i)
#pragma unroll
            for (int e = 0; e < 4; ++e) d[i * 4 + e] = yacc[i][e];
    }
    __syncthreads();
    if (w < 8) {
        const float* s = stag + (w * 32 + lane) * 32;
        float* yr0 = Yg + ((size_t)((b * T_DIM + ig0) * H_DIM) + h) * P_DIM;
        float* yr1 = Yg + ((size_t)((b * T_DIM + ig1) * H_DIM) + h) * P_DIM;
#pragma unroll
        for (int pf = 0; pf < 8; ++pf) {
            int p0 = 8 * pf + (lane & 3) * 2;
            *(float2*)(yr0 + p0) = make_float2(yacc[pf][0] + s[pf * 4 + 0], yacc[pf][1] + s[pf * 4 + 1]);
            *(float2*)(yr1 + p0) = make_float2(yacc[pf][2] + s[pf * 4 + 2], yacc[pf][3] + s[pf * 4 + 3]);
        }
    }
}

// ---------------------------------------------------------------------------
// final_state partials + reduce (fp32, unchanged)
// ---------------------------------------------------------------------------
#define PC 132
#define PX 68
__global__ void __launch_bounds__(256) state_kernel(
    const float* __restrict__ xg, const float* __restrict__ Bg)
{
    int split = blockIdx.x;
    int bh    = blockIdx.y;
    int b = bh >> 5, h = bh & 31;
    const float* acs = g_Acs + (size_t)bh * T_DIM;
    float atot = acs[T_DIM - 1];

    __shared__ float sx[32 * PX];
    __shared__ float sb[32 * PC];
    __shared__ float sd[32];

    int tid = threadIdx.x;
    int i2 = tid >> 4, j2 = tid & 15;
    float acc[4][8];
#pragma unroll
    for (int a = 0; a < 4; a++)
#pragma unroll
        for (int c2 = 0; c2 < 8; c2++) acc[a][c2] = 0.f;

    const int tspan = T_DIM / NSPLIT;
    const int t0base = split * tspan;
    for (int t0 = t0base; t0 < t0base + tspan; t0 += 32) {
        __syncthreads();
        for (int idx = tid; idx < 32 * 16; idx += 256) {
            int row = idx >> 4, q = idx & 15;
            *(float4*)(sx + row * PX + q * 4) =
                *(const float4*)(xg + ((size_t)((b * T_DIM + t0 + row) * H_DIM) + h) * P_DIM + q * 4);
        }
        for (int idx = tid; idx < 32 * 32; idx += 256) {
            int row = idx >> 5, q = idx & 31;
            *(float4*)(sb + row * PC + q * 4) =
                *(const float4*)(Bg + ((size_t)((b * T_DIM + t0 + row) * H_DIM) + h) * N_DIM + q * 4);
        }
        if (tid < 32) sd[tid] = __expf(atot - acs[t0 + tid]);
        __syncthreads();

        for (int tt = 0; tt < 32; ++tt) {
            float d = sd[tt];
            float a0[4], b0[8];
#pragma unroll
            for (int di = 0; di < 4; di++) a0[di] = sx[tt * PX + i2 + 16 * di] * d;
#pragma unroll
            for (int dj = 0; dj < 8; dj++) b0[dj] = sb[tt * PC + j2 + 16 * dj];
#pragma unroll
            for (int di = 0; di < 4; di++)
#pragma unroll
                for (int dj = 0; dj < 8; dj++)
                    acc[di][dj] += a0[di] * b0[dj];
        }
    }

    float* outp = g_part + ((size_t)split * BH + bh) * (P_DIM * N_DIM);
#pragma unroll
    for (int di = 0; di < 4; di++)
#pragma unroll
        for (int dj = 0; dj < 8; dj++)
            outp[(i2 + 16 * di) * N_DIM + (j2 + 16 * dj)] = acc[di][dj];
}

__global__ void reduce_kernel(float* __restrict__ out) {
    int idx = blockIdx.x * 256 + threadIdx.x;
    if (idx < FS_SIZE) {
        float s = 0.f;
#pragma unroll
        for (int sp = 0; sp < NSPLIT; ++sp)
            s += g_part[(size_t)sp * FS_SIZE + idx];
        out[Y_SIZE + idx] = s;
    }
}

// ---------------------------------------------------------------------------
extern "C" void kernel_launch(void* const* d_in, const int* in_sizes, int n_in,
                              void* d_out, int out_size) {
    const float* xg  = (const float*)d_in[0];
    const float* Ag  = (const float*)d_in[1];
    const float* Bg  = (const float*)d_in[2];
    const float* Cg  = (const float*)d_in[3];
    const float* Lm  = (const float*)d_in[4];
    const float* msf = (const float*)d_in[5];
    float* out = (float*)d_out;

    acs_kernel<<<BH, 1024>>>(Ag);

    cudaFuncSetAttribute(ssd_mma_kernel,
                         cudaFuncAttributeMaxDynamicSharedMemorySize, SMEM_BYTES);
    ssd_mma_kernel<<<dim3(8, BH), THREADS, SMEM_BYTES>>>(xg, Bg, Cg, Lm, msf, out);

    state_kernel<<<dim3(NSPLIT, BH), 256>>>(xg, Bg);
    reduce_kernel<<<(FS_SIZE + 255) / 256, 256>>>(out);
}

// round 7
// speedup vs baseline: 3.1703x; 1.0781x over previous
#include <cuda_runtime.h>
#include <cuda_fp16.h>
#include <cstdint>

// Problem constants
#define B_DIM 2
#define T_DIM 1024
#define H_DIM 32
#define P_DIM 64
#define N_DIM 128
#define BH (B_DIM * H_DIM)
#define Y_SIZE (B_DIM * T_DIM * H_DIM * P_DIM)
#define FS_SIZE (BH * P_DIM * N_DIM)
#define NSPLIT 8

__device__ float g_Acs[BH * T_DIM];
__device__ float g_part[NSPLIT * FS_SIZE];

// ---------------- helpers ----------------
__device__ __forceinline__ uint32_t smem_u32(const void* p) {
    uint32_t a;
    asm("{ .reg .u64 t; cvta.to.shared.u64 t, %1; cvt.u32.u64 %0, t; }" : "=r"(a) : "l"(p));
    return a;
}
__device__ __forceinline__ void ldsm4(uint32_t& r0, uint32_t& r1, uint32_t& r2, uint32_t& r3, uint32_t addr) {
    asm volatile("ldmatrix.sync.aligned.m8n8.x4.shared.b16 {%0,%1,%2,%3}, [%4];"
                 : "=r"(r0), "=r"(r1), "=r"(r2), "=r"(r3) : "r"(addr));
}
__device__ __forceinline__ void mma16816(float* d, uint32_t a0, uint32_t a1, uint32_t a2, uint32_t a3,
                                         uint32_t b0, uint32_t b1) {
    asm volatile("mma.sync.aligned.m16n8k16.row.col.f32.f16.f16.f32 "
                 "{%0,%1,%2,%3}, {%4,%5,%6,%7}, {%8,%9}, {%0,%1,%2,%3};"
                 : "+f"(d[0]), "+f"(d[1]), "+f"(d[2]), "+f"(d[3])
                 : "r"(a0), "r"(a1), "r"(a2), "r"(a3), "r"(b0), "r"(b1));
}
// pack two fp32 -> f16x2 (x in low half)
__device__ __forceinline__ uint32_t pack_h2(float x, float y) {
    uint32_t r;
    asm("cvt.rn.f16x2.f32 %0, %1, %2;" : "=r"(r) : "f"(y), "f"(x));
    return r;
}

// SMEM layout. Pitches keep ldmatrix rows in distinct 16B groups.
#define PCH 272
#define PXH 144
#define O_ECOL 0                              // 2 x 64 floats
#define O_C    1024                           // 128 * PCH = 34816 (fp16 C)
#define O_B    (O_C + 128 * PCH)              // 35840 ; 2 bufs x 17408
#define O_X    (O_B + 2 * 17408)              // 70656 ; 2 bufs x 9216
#define SMEM_BYTES (O_X + 2 * 9216)           // 89088

#define THREADS 512

// ---------------------------------------------------------------------------
__global__ void __launch_bounds__(1024) acs_kernel(const float* __restrict__ A) {
    int bh = blockIdx.x;
    int b = bh >> 5, h = bh & 31;
    __shared__ float buf[2][T_DIM];
    int t = threadIdx.x;
    buf[0][t] = A[(size_t)(b * T_DIM + t) * H_DIM + h];
    __syncthreads();
    int src = 0;
    for (int off = 1; off < T_DIM; off <<= 1) {
        float v = buf[src][t];
        if (t >= off) v += buf[src][t - off];
        buf[src ^ 1][t] = v;
        src ^= 1;
        __syncthreads();
    }
    g_Acs[bh * T_DIM + t] = buf[src][t];
}

// ---------------------------------------------------------------------------
// Main kernel: block = (r2, bh), 16 warps. Warp pair (w, w+8) shares 16 rows,
// splits the 64 j-columns. Single-pass fp16 both stages (C, B, X, Ms each
// rounded once). Double-buffered B/X tiles, register-pipelined LDGs.
// ---------------------------------------------------------------------------
__global__ void __launch_bounds__(THREADS, 1)
ssd_mma_kernel(const float* __restrict__ xg, const float* __restrict__ Bg,
               const float* __restrict__ Cg, const float* __restrict__ Lm,
               const float* __restrict__ msfp, float* __restrict__ Yg)
{
    extern __shared__ char smb[];
    float* ecolb = (float*)(smb + O_ECOL);
    const uint32_t sb = smem_u32(smb);

    const int r2 = 7 - (int)blockIdx.x;
    const int bh = blockIdx.y;
    const int b = bh >> 5, h = bh & 31;
    const int tid = threadIdx.x;
    const int w = tid >> 5, lane = tid & 31;
    const int wr = w & 7;
    const int joff = (w >> 3) * 32;
    const float msf = *msfp;
    const float* acs = g_Acs + (size_t)bh * T_DIM;
    const int ncols = 2 * r2 + 2;
    const int row0 = r2 * 128;

    // ---- load + round C (128x128) once -> fp16 tile ----
    for (int u = 0; u < 8; ++u) {
        int idx = tid + u * THREADS;
        int row = idx >> 5, q = idx & 31;
        float4 v = *(const float4*)(Cg + ((size_t)((b * T_DIM + row0 + row) * H_DIM) + h) * N_DIM + q * 4);
        *(uint2*)(smb + O_C + row * PCH + q * 8) =
            make_uint2(pack_h2(v.x, v.y), pack_h2(v.z, v.w));
    }

    // lane geometry
    const int g = lane >> 3;
    const int lrow = (g & 1) * 8 + (lane & 7);
    const int lcolB = (g >> 1) * 16;
    const uint32_t aC = sb + O_C + (wr * 16 + lrow) * PCH + lcolB;

    const int ig0 = row0 + wr * 16 + (lane >> 2);
    const int ig1 = ig0 + 8;
    const float av0 = acs[ig0], av1 = acs[ig1];
    const int jmaxRow = row0 + wr * 16 + 15;
    const float* lr0 = Lm + ((size_t)bh * T_DIM + ig0) * T_DIM;
    const float* lr1 = lr0 + 8 * T_DIM;

    float yacc[8][4];
#pragma unroll
    for (int i = 0; i < 8; i++)
#pragma unroll
        for (int e = 0; e < 4; e++) yacc[i][e] = 0.f;

    // ---- staging registers ----
    float4 bR[4], xR[2];
    auto loadBX = [&](int c) {
#pragma unroll
        for (int u = 0; u < 4; ++u) {
            int idx = tid + u * THREADS;
            int row = idx >> 5, q = idx & 31;
            bR[u] = *(const float4*)(Bg + ((size_t)((b * T_DIM + c * 64 + row) * H_DIM) + h) * N_DIM + q * 4);
        }
#pragma unroll
        for (int u = 0; u < 2; ++u) {
            int idx = tid + u * THREADS;
            int j = idx >> 4, q = idx & 15;
            xR[u] = *(const float4*)(xg + ((size_t)((b * T_DIM + c * 64 + j) * H_DIM) + h) * P_DIM + q * 4);
        }
    };
    auto storeBX = [&](int nb) {
        char* bbase = smb + O_B + nb * 17408;
#pragma unroll
        for (int u = 0; u < 4; ++u) {
            int idx = tid + u * THREADS;
            int row = idx >> 5, q = idx & 31;
            *(uint2*)(bbase + row * PCH + q * 8) =
                make_uint2(pack_h2(bR[u].x, bR[u].y), pack_h2(bR[u].z, bR[u].w));
        }
        char* xbase = smb + O_X + nb * 9216;
#pragma unroll
        for (int u = 0; u < 2; ++u) {
            int idx = tid + u * THREADS;
            int j = idx >> 4, q = idx & 15;
            const float* vp = (const float*)&xR[u];
#pragma unroll
            for (int e = 0; e < 4; ++e) {
                int p = 4 * q + e;
                *(__half*)(xbase + p * PXH + j * 2) = __float2half_rn(vp[e]);
            }
        }
    };

    // ---- prologue ----
    loadBX(0);
    float ecv = 0.f;
    if (tid < 64) ecv = __expf(acs[0] - acs[tid]);
    storeBX(0);
    if (tid < 64) ecolb[tid] = ecv;
    __syncthreads();

    for (int c = 0; c < ncols; ++c) {
        const int cur = c & 1;
        const bool more = (c + 1 < ncols);
        if (more) loadBX(c + 1);
        float ecn = 0.f;
        if (more && tid < 64) ecn = __expf(__ldg(acs + (c + 1) * 64) - __ldg(acs + (c + 1) * 64 + tid));

        const bool active = (c * 64 <= jmaxRow);
        if (active) {
            // ---- Lm prefetch ----
            float2 L0[4], L1[4];
            const float* l0p = lr0 + c * 64 + joff;
            const float* l1p = lr1 + c * 64 + joff;
#pragma unroll
            for (int nf = 0; nf < 4; ++nf) {
                int jl = 8 * nf + (lane & 3) * 2;
                L0[nf] = *(const float2*)(l0p + jl);
                L1[nf] = *(const float2*)(l1p + jl);
            }
            const float aj0 = __ldg(acs + c * 64);

            // ---- Stage 1: S(16x32) = C·B^T (single fp16 pass) ----
            float sacc[4][4];
#pragma unroll
            for (int i = 0; i < 4; i++)
#pragma unroll
                for (int e = 0; e < 4; e++) sacc[i][e] = 0.f;

            const uint32_t bBase = sb + O_B + cur * 17408 + (joff + lrow) * PCH + lcolB;
#pragma unroll
            for (int ks = 0; ks < 8; ++ks) {
                uint32_t a0, a1, a2, a3;
                ldsm4(a0, a1, a2, a3, aC + ks * 32);
#pragma unroll
                for (int nf2 = 0; nf2 < 2; ++nf2) {
                    uint32_t b0, b1, b2, b3;
                    ldsm4(b0, b1, b2, b3, bBase + nf2 * (16 * PCH) + ks * 32);
                    mma16816(sacc[2 * nf2],     a0, a1, a2, a3, b0, b2);
                    mma16816(sacc[2 * nf2 + 1], a0, a1, a2, a3, b1, b3);
                }
            }

            // ---- Epilogue: mask + round Ms to fp16 A-frags ----
            const float erow0 = __expf(av0 - aj0);
            const float erow1 = __expf(av1 - aj0);
            const float* ecol = ecolb + cur * 64;
            uint32_t mhi[8];
#pragma unroll
            for (int nf = 0; nf < 4; ++nf) {
                int jl = joff + 8 * nf + (lane & 3) * 2;
                int jgv = c * 64 + jl;
                float2 ec = *(const float2*)(ecol + jl);
                float f00 = (jgv     <= ig0) ? fmaf(msf, L0[nf].x, erow0 * ec.x) : 0.f;
                float f01 = (jgv + 1 <= ig0) ? fmaf(msf, L0[nf].y, erow0 * ec.y) : 0.f;
                float f10 = (jgv     <= ig1) ? fmaf(msf, L1[nf].x, erow1 * ec.x) : 0.f;
                float f11 = (jgv + 1 <= ig1) ? fmaf(msf, L1[nf].y, erow1 * ec.y) : 0.f;
                int ks = nf >> 1, part = nf & 1;
                int i0 = ks * 4 + part * 2;
                mhi[i0]     = pack_h2(sacc[nf][0] * f00, sacc[nf][1] * f01);
                mhi[i0 + 1] = pack_h2(sacc[nf][2] * f10, sacc[nf][3] * f11);
            }

            // ---- Stage 2: Y += Ms·X (single fp16 pass) ----
            const uint32_t xBase = sb + O_X + cur * 9216 + lrow * PXH + joff * 2 + lcolB;
#pragma unroll
            for (int ks = 0; ks < 2; ++ks) {
#pragma unroll
                for (int pf2 = 0; pf2 < 4; ++pf2) {
                    uint32_t b0, b1, b2, b3;
                    ldsm4(b0, b1, b2, b3, xBase + pf2 * (16 * PXH) + ks * 32);
                    mma16816(yacc[2 * pf2],     mhi[4 * ks], mhi[4 * ks + 1], mhi[4 * ks + 2], mhi[4 * ks + 3], b0, b2);
                    mma16816(yacc[2 * pf2 + 1], mhi[4 * ks], mhi[4 * ks + 1], mhi[4 * ks + 2], mhi[4 * ks + 3], b1, b3);
                }
            }
        }

        if (more) {
            storeBX((c + 1) & 1);
            if (tid < 64) ecolb[((c + 1) & 1) * 64 + tid] = ecn;
        }
        __syncthreads();
    }

    // ---- reduce warp pairs (w, w+8) and write Y ----
    float* stag = (float*)(smb + O_B);
    if (w >= 8) {
        float* d = stag + ((w - 8) * 32 + lane) * 32;
#pragma unroll
        for (int i = 0; i < 8; ++i)
#pragma unroll
            for (int e = 0; e < 4; ++e) d[i * 4 + e] = yacc[i][e];
    }
    __syncthreads();
    if (w < 8) {
        const float* s = stag + (w * 32 + lane) * 32;
        float* yr0 = Yg + ((size_t)((b * T_DIM + ig0) * H_DIM) + h) * P_DIM;
        float* yr1 = Yg + ((size_t)((b * T_DIM + ig1) * H_DIM) + h) * P_DIM;
#pragma unroll
        for (int pf = 0; pf < 8; ++pf) {
            int p0 = 8 * pf + (lane & 3) * 2;
            *(float2*)(yr0 + p0) = make_float2(yacc[pf][0] + s[pf * 4 + 0], yacc[pf][1] + s[pf * 4 + 1]);
            *(float2*)(yr1 + p0) = make_float2(yacc[pf][2] + s[pf * 4 + 2], yacc[pf][3] + s[pf * 4 + 3]);
        }
    }
}

// ---------------------------------------------------------------------------
// final_state partials + reduce (fp32, unchanged)
// ---------------------------------------------------------------------------
#define PC 132
#define PX 68
__global__ void __launch_bounds__(256) state_kernel(
    const float* __restrict__ xg, const float* __restrict__ Bg)
{
    int split = blockIdx.x;
    int bh    = blockIdx.y;
    int b = bh >> 5, h = bh & 31;
    const float* acs = g_Acs + (size_t)bh * T_DIM;
    float atot = acs[T_DIM - 1];

    __shared__ float sx[32 * PX];
    __shared__ float sb[32 * PC];
    __shared__ float sd[32];

    int tid = threadIdx.x;
    int i2 = tid >> 4, j2 = tid & 15;
    float acc[4][8];
#pragma unroll
    for (int a = 0; a < 4; a++)
#pragma unroll
        for (int c2 = 0; c2 < 8; c2++) acc[a][c2] = 0.f;

    const int tspan = T_DIM / NSPLIT;
    const int t0base = split * tspan;
    for (int t0 = t0base; t0 < t0base + tspan; t0 += 32) {
        __syncthreads();
        for (int idx = tid; idx < 32 * 16; idx += 256) {
            int row = idx >> 4, q = idx & 15;
            *(float4*)(sx + row * PX + q * 4) =
                *(const float4*)(xg + ((size_t)((b * T_DIM + t0 + row) * H_DIM) + h) * P_DIM + q * 4);
        }
        for (int idx = tid; idx < 32 * 32; idx += 256) {
            int row = idx >> 5, q = idx & 31;
            *(float4*)(sb + row * PC + q * 4) =
                *(const float4*)(Bg + ((size_t)((b * T_DIM + t0 + row) * H_DIM) + h) * N_DIM + q * 4);
        }
        if (tid < 32) sd[tid] = __expf(atot - acs[t0 + tid]);
        __syncthreads();

        for (int tt = 0; tt < 32; ++tt) {
            float d = sd[tt];
            float a0[4], b0[8];
#pragma unroll
            for (int di = 0; di < 4; di++) a0[di] = sx[tt * PX + i2 + 16 * di] * d;
#pragma unroll
            for (int dj = 0; dj < 8; dj++) b0[dj] = sb[tt * PC + j2 + 16 * dj];
#pragma unroll
            for (int di = 0; di < 4; di++)
#pragma unroll
                for (int dj = 0; dj < 8; dj++)
                    acc[di][dj] += a0[di] * b0[dj];
        }
    }

    float* outp = g_part + ((size_t)split * BH + bh) * (P_DIM * N_DIM);
#pragma unroll
    for (int di = 0; di < 4; di++)
#pragma unroll
        for (int dj = 0; dj < 8; dj++)
            outp[(i2 + 16 * di) * N_DIM + (j2 + 16 * dj)] = acc[di][dj];
}

__global__ void reduce_kernel(float* __restrict__ out) {
    int idx = blockIdx.x * 256 + threadIdx.x;
    if (idx < FS_SIZE) {
        float s = 0.f;
#pragma unroll
        for (int sp = 0; sp < NSPLIT; ++sp)
            s += g_part[(size_t)sp * FS_SIZE + idx];
        out[Y_SIZE + idx] = s;
    }
}

// ---------------------------------------------------------------------------
extern "C" void kernel_launch(void* const* d_in, const int* in_sizes, int n_in,
                              void* d_out, int out_size) {
    const float* xg  = (const float*)d_in[0];
    const float* Ag  = (const float*)d_in[1];
    const float* Bg  = (const float*)d_in[2];
    const float* Cg  = (const float*)d_in[3];
    const float* Lm  = (const float*)d_in[4];
    const float* msf = (const float*)d_in[5];
    float* out = (float*)d_out;

    acs_kernel<<<BH, 1024>>>(Ag);

    cudaFuncSetAttribute(ssd_mma_kernel,
                         cudaFuncAttributeMaxDynamicSharedMemorySize, SMEM_BYTES);
    ssd_mma_kernel<<<dim3(8, BH), THREADS, SMEM_BYTES>>>(xg, Bg, Cg, Lm, msf, out);

    state_kernel<<<dim3(NSPLIT, BH), 256>>>(xg, Bg);
    reduce_kernel<<<(FS_SIZE + 255) / 256, 256>>>(out);
}